// round 17
// baseline (speedup 1.0000x reference)
#include <cuda_runtime.h>
#include <cstdint>

// Problem constants (fixed by the reference: SHAPE = (8192, 4096), P = 0.3)
#define N_ELEMS   (8192 * 4096)        // 33,554,432 floats
#define N_WORDS   (N_ELEMS / 32)       // 1,048,576 uint32 mask words = 4 MB
#define N_FLOAT4  (N_ELEMS / 4)        // 8,388,608 float4s

// Scratch: 1 bit per element, 4 MB -> stays L2-resident so every RED.OR is
// an L2-hit RMW (~2 cyc/LTS slot; the measured scatter floor). Zero at
// module load; apply re-zeroes it every pass (self-cleaning).
__device__ uint32_t g_mask[N_WORDS];

// ---------------------------------------------------------------------------
// Kernel 1: scatter-set bits. Flat, one int4 idx load + 4 fire-and-forget
// RED.ORs per thread. PDL both ways:
//   - front-issues its idx load (independent of the previous apply), THEN
//     cudaGridDependencySynchronize() before the REDs (which must see the
//     previous apply's mask cleans when replayed in a graph loop);
//   - triggers completion after its REDs so the apply can ramp early.
// ---------------------------------------------------------------------------
__global__ void set_bits_kernel(const int4* __restrict__ idx4, int n_quads,
                                int k) {
    int i = blockIdx.x * blockDim.x + threadIdx.x;
    bool active = (i < n_quads);
    int4 v;
    if (active) v = __ldcs(&idx4[i]);   // overlaps previous apply's tail

    cudaGridDependencySynchronize();     // mask cleans must be visible

    if (active) {
        unsigned int a = (unsigned int)v.x;
        unsigned int b = (unsigned int)v.y;
        unsigned int c = (unsigned int)v.z;
        unsigned int d = (unsigned int)v.w;
        atomicOr(&g_mask[a >> 5], 1u << (a & 31));
        atomicOr(&g_mask[b >> 5], 1u << (b & 31));
        atomicOr(&g_mask[c >> 5], 1u << (c & 31));
        atomicOr(&g_mask[d >> 5], 1u << (d & 31));
    }
    // tail (k % 4 != 0)
    if (i == 0) {
        const int* idx = (const int*)idx4;
        for (int j = n_quads * 4; j < k; j++) {
            unsigned int a = (unsigned int)idx[j];
            atomicOr(&g_mask[a >> 5], 1u << (a & 31));
        }
    }
    cudaTriggerProgrammaticLaunchCompletion();
}

// ---------------------------------------------------------------------------
// Kernel 2: fused copy + masked zero + mask self-clean (best-measured
// config: 256 threads, ILP=4 block-strided, 1024 consecutive float4s per
// block, coalesced). PDL ordering: issue ALL X loads first (legal overlap
// with the scatter), then cudaGridDependencySynchronize(), then the mask.
// 8 adjacent same-warp threads share one mask word; the (tid&7)==0 lane
// cleans AFTER the group's mask loads (same warp -> program order).
// Triggers completion right after the cleans so the next replay's scatter
// can front-run its idx loads under this kernel's store drain.
// ---------------------------------------------------------------------------
__global__ void __launch_bounds__(256, 8)
apply_mask_kernel(const float4* __restrict__ X, float4* __restrict__ out) {
    int tid = threadIdx.x;
    int base = blockIdx.x * 1024 + tid;
    int i0 = base, i1 = base + 256, i2 = base + 512, i3 = base + 768;

    // X loads first: independent of the scatter, fly under its RED drain.
    float4 v0 = __ldcs(&X[i0]);
    float4 v1 = __ldcs(&X[i1]);
    float4 v2 = __ldcs(&X[i2]);
    float4 v3 = __ldcs(&X[i3]);

    cudaGridDependencySynchronize();     // scatter's REDs must be visible

    uint32_t w0 = g_mask[i0 >> 3];
    uint32_t w1 = g_mask[i1 >> 3];
    uint32_t w2 = g_mask[i2 >> 3];
    uint32_t w3 = g_mask[i3 >> 3];

    uint32_t n0 = w0 >> ((i0 & 7) * 4);
    if (n0 & 1u) v0.x = 0.0f;
    if (n0 & 2u) v0.y = 0.0f;
    if (n0 & 4u) v0.z = 0.0f;
    if (n0 & 8u) v0.w = 0.0f;
    __stcs(&out[i0], v0);

    uint32_t n1 = w1 >> ((i1 & 7) * 4);
    if (n1 & 1u) v1.x = 0.0f;
    if (n1 & 2u) v1.y = 0.0f;
    if (n1 & 4u) v1.z = 0.0f;
    if (n1 & 8u) v1.w = 0.0f;
    __stcs(&out[i1], v1);

    uint32_t n2 = w2 >> ((i2 & 7) * 4);
    if (n2 & 1u) v2.x = 0.0f;
    if (n2 & 2u) v2.y = 0.0f;
    if (n2 & 4u) v2.z = 0.0f;
    if (n2 & 8u) v2.w = 0.0f;
    __stcs(&out[i2], v2);

    uint32_t n3 = w3 >> ((i3 & 7) * 4);
    if (n3 & 1u) v3.x = 0.0f;
    if (n3 & 2u) v3.y = 0.0f;
    if (n3 & 4u) v3.z = 0.0f;
    if (n3 & 8u) v3.w = 0.0f;
    __stcs(&out[i3], v3);

    // self-clean for next graph replay (one lane per 8-thread group cleans
    // that group's four mask words; same warp as all readers of those words)
    if ((tid & 7) == 0) {
        g_mask[i0 >> 3] = 0u;
        g_mask[i1 >> 3] = 0u;
        g_mask[i2 >> 3] = 0u;
        g_mask[i3 >> 3] = 0u;
    }

    cudaTriggerProgrammaticLaunchCompletion();
}

// Launch helper with programmatic stream serialization + plain fallback.
template <typename... Args>
static void launch_pdl(void (*kern)(Args...), dim3 grid, dim3 block,
                       Args... args) {
    cudaLaunchConfig_t cfg = {};
    cfg.gridDim = grid;
    cfg.blockDim = block;
    cudaLaunchAttribute attr[1];
    attr[0].id = cudaLaunchAttributeProgrammaticStreamSerialization;
    attr[0].val.programmaticStreamSerializationAllowed = 1;
    cfg.attrs = attr;
    cfg.numAttrs = 1;
    if (cudaLaunchKernelEx(&cfg, kern, args...) != cudaSuccess) {
        kern<<<grid, block>>>(args...);
    }
}

extern "C" void kernel_launch(void* const* d_in, const int* in_sizes, int n_in,
                              void* d_out, int out_size) {
    const float* X = (const float*)d_in[0];
    const int* drop_idx = (const int*)d_in[1];   // JAX x64-disabled => int32
    int k = in_sizes[1];                          // number of indices
    float* out = (float*)d_out;

    int n_quads = k / 4;
    int blocks1 = (n_quads + 255) / 256;          // flat, wide

    // 1) scatter bits (PSS: may start while previous replay's apply drains;
    //    gridsync inside orders its REDs after the mask cleans)
    launch_pdl(set_bits_kernel, dim3(blocks1), dim3(256),
               (const int4*)drop_idx, n_quads, k);

    // 2) fused copy + zero + mask clean (PSS: ramps under the RED drain)
    launch_pdl(apply_mask_kernel, dim3(N_FLOAT4 / 1024), dim3(256),
               (const float4*)X, (float4*)out);
}